// round 16
// baseline (speedup 1.0000x reference)
#include <cuda_runtime.h>
#include <cstddef>

// DiffEqLayer scan: T steps, B chains, 4 threads/chain (role r = output row).
// Role-relative state hh[k] = h[r^k]; weight columns permuted at load so all
// per-step code is index-uniform. Dot products AND epilogue packed into f32x2
// (FFMA2); quad communication via single-depth parallel shfl_xor (masks 1/2/3).
// Loop unrolled 2x so the input-buffer rotate is renamed away by ptxas.
// Block = 32 (1 warp/CTA): 1024 CTAs over 148 SMs -> near-perfect wave balance.
// W1 row indices are taken from the adj_mat INPUT (d_in[9]) at prologue time,
// not from a hand-derived table: row for partner r^k is adj_mat[r][r^k]; rows
// for the two input temps are adj_mat[r][4], adj_mat[r][5]. Diagonal entries
// are never read (their diffusion terms vanish since temps[i]-h[i]=0).

typedef unsigned long long u64;

__device__ __forceinline__ float ftanh(float x) {
    float y;
    asm("tanh.approx.f32 %0, %1;" : "=f"(y) : "f"(x));
    return y;
}
__device__ __forceinline__ u64 pk(float lo, float hi) {
    u64 r;
    asm("mov.b64 %0, {%1, %2};" : "=l"(r) : "f"(lo), "f"(hi));
    return r;
}
__device__ __forceinline__ u64 pk1(float v) {  // (v, v)
    u64 r;
    asm("mov.b64 %0, {%1, %1};" : "=l"(r) : "f"(v));
    return r;
}
__device__ __forceinline__ void upk(u64 p, float& lo, float& hi) {
    asm("mov.b64 {%0, %1}, %2;" : "=f"(lo), "=f"(hi) : "l"(p));
}
__device__ __forceinline__ u64 ffma2(u64 a, u64 b, u64 c) {
    u64 d;
    asm("fma.rn.f32x2 %0, %1, %2, %3;" : "=l"(d) : "l"(a), "l"(b), "l"(c));
    return d;
}
__device__ __forceinline__ u64 fmul2(u64 a, u64 b) {
    u64 d;
    asm("mul.rn.f32x2 %0, %1, %2;" : "=l"(d) : "l"(a), "l"(b));
    return d;
}
__device__ __forceinline__ u64 fadd2(u64 a, u64 b) {
    u64 d;
    asm("add.rn.f32x2 %0, %1, %2;" : "=l"(d) : "l"(a), "l"(b));
    return d;
}
__device__ __forceinline__ float ldcs(const float* p) {
    float v;
    asm volatile("ld.global.cs.f32 %0, [%1];" : "=f"(v) : "l"(p));
    return v;
}
__device__ __forceinline__ void stcs(float* p, float v) {
    asm volatile("st.global.cs.f32 [%0], %1;" :: "l"(p), "f"(v));
}

__global__ void __launch_bounds__(32)
diffeq_scan_kernel(const float* __restrict__ inp,    // [T, B, 7]
                   const float* __restrict__ state,  // [B, 4]
                   const float* __restrict__ caps,   // [4]
                   const float* __restrict__ W1,     // [15, 11]
                   const float* __restrict__ b1,     // [15]
                   const float* __restrict__ Wp1,    // [8, 11]
                   const float* __restrict__ bp1,    // [8]
                   const float* __restrict__ Wp2,    // [4, 8]
                   const float* __restrict__ bp2,    // [4]
                   const int*   __restrict__ adj,    // [4, 6]
                   float* __restrict__ out,          // [T*B*4 + B*4]
                   int B, int T)
{
    const int tid = blockIdx.x * blockDim.x + threadIdx.x;
    const int b = tid >> 2;
    const int r = tid & 3;
    if (b >= B) return;

    // ---- W1 row indices for this role, straight from adj_mat -------------
    // m=0..2: conductance vs quad partner r^(m+1); m=3,4: vs input temps.
    int w1rows[5];
#pragma unroll
    for (int m = 0; m < 3; ++m) w1rows[m] = __ldg(&adj[r * 6 + (r ^ (m + 1))]);
    w1rows[3] = __ldg(&adj[r * 6 + 4]);
    w1rows[4] = __ldg(&adj[r * 6 + 5]);

    // ---- packed loop-invariant weights -----------------------------------
    // Dot chains: P0 = (c0, c1), P1 = (c2, c3), P2 = (c4, p0), scalar: p1.
    // Conductance rows pre-scaled by 0.5: sigmoid(z) = 0.5*tanh(0.5 z)+0.5.
    float wrow[5][11];  // staging: c-rows (scaled)
#pragma unroll
    for (int m = 0; m < 5; ++m) {
        const int row = w1rows[m];
#pragma unroll
        for (int k = 0; k < 7; ++k) wrow[m][k] = 0.5f * __ldg(&W1[row * 11 + k]);
#pragma unroll
        for (int k = 0; k < 4; ++k)
            wrow[m][7 + k] = 0.5f * __ldg(&W1[row * 11 + 7 + (r ^ k)]);
    }
    float prow[2][11];  // Wp1 rows 2r, 2r+1 (unscaled)
#pragma unroll
    for (int m = 0; m < 2; ++m) {
        const int row = 2 * r + m;
#pragma unroll
        for (int k = 0; k < 7; ++k) prow[m][k] = __ldg(&Wp1[row * 11 + k]);
#pragma unroll
        for (int k = 0; k < 4; ++k)
            prow[m][7 + k] = __ldg(&Wp1[row * 11 + 7 + (r ^ k)]);
    }
    u64 ww0[11], ww1[11], ww2[11];
    float wS[11];
#pragma unroll
    for (int k = 0; k < 11; ++k) {
        ww0[k] = pk(wrow[0][k], wrow[1][k]);
        ww1[k] = pk(wrow[2][k], wrow[3][k]);
        ww2[k] = pk(wrow[4][k], prow[0][k]);
        wS[k]  = prow[1][k];
    }
    const u64 bb0  = pk(0.5f * __ldg(&b1[w1rows[0]]), 0.5f * __ldg(&b1[w1rows[1]]));
    const u64 bb1_ = pk(0.5f * __ldg(&b1[w1rows[2]]), 0.5f * __ldg(&b1[w1rows[3]]));
    const u64 bb2_ = pk(0.5f * __ldg(&b1[w1rows[4]]), __ldg(&bp1[2 * r]));
    const float bS = __ldg(&bp1[2 * r + 1]);

    // Wp2 columns {2r, 2r+1}, rows role-relative; packed over k-pairs.
    const u64 wpa01 = pk(__ldg(&Wp2[(r ^ 0) * 8 + 2 * r]), __ldg(&Wp2[(r ^ 1) * 8 + 2 * r]));
    const u64 wpa23 = pk(__ldg(&Wp2[(r ^ 2) * 8 + 2 * r]), __ldg(&Wp2[(r ^ 3) * 8 + 2 * r]));
    const u64 wpb01 = pk(__ldg(&Wp2[(r ^ 0) * 8 + 2 * r + 1]), __ldg(&Wp2[(r ^ 1) * 8 + 2 * r + 1]));
    const u64 wpb23 = pk(__ldg(&Wp2[(r ^ 2) * 8 + 2 * r + 1]), __ldg(&Wp2[(r ^ 3) * 8 + 2 * r + 1]));
    // bpp2 folded into PPlo's lo lane; hi lane MUST be 0 (PP1 is shipped raw).
    const u64 bpc = pk(__ldg(&bp2[r]), 0.0f);

    // gain = 0.5 * 10^caps[r]; gainH = 0.5*gain absorbs the sigmoid 0.5 factor
    const float gain  = 0.5f * exp2f(__ldg(&caps[r]) * 3.321928094887362f);
    const float gainH = 0.5f * gain;
    const u64 negone2 = pk(-1.0f, -1.0f);

    // ---- role-relative state ---------------------------------------------
    float hh0 = __ldg(&state[b * 4 + r]);
    float hh1 = __ldg(&state[b * 4 + (r ^ 1)]);
    float hh2 = __ldg(&state[b * 4 + (r ^ 2)]);
    float hh3 = __ldg(&state[b * 4 + (r ^ 3)]);
    u64 hhx0 = pk1(hh0), hhx1 = pk1(hh1), hhx2 = pk1(hh2), hhx3 = pk1(hh3);

    const size_t xstride = (size_t)B * 7;
    const float* xp = inp + (size_t)b * 7;
    float x[7];   // scalar copy (for p1 chain and temp-diff)
    u64 xx[7];    // packed copy (for f32x2 chains)
#pragma unroll
    for (int k = 0; k < 7; ++k) { x[k] = ldcs(&xp[k]); xx[k] = pk1(x[k]); }

    const size_t ostride = (size_t)B * 4;
    float* outp = out + (size_t)b * 4 + r;

#pragma unroll 2
    for (int t = 0; t < T; ++t) {
        // prefetch next step's input first (gets into L1tex queue earliest)
        float xn[7];
        const float* xnp = xp + xstride;
        if (t + 1 < T) {
#pragma unroll
            for (int k = 0; k < 7; ++k) xn[k] = ldcs(&xnp[k]);
        }

        // outputs[t] = h(t) (state BEFORE update); streaming store
        stcs(outp, hh0);

        // ---- packed dot products (x terms first, h terms last so the
        //      previous step's allgather latency hides under them) ----
        u64 a0 = bb0, a1 = bb1_, a2 = bb2_;
        float aS = bS;
#pragma unroll
        for (int k = 0; k < 7; ++k) {
            a0 = ffma2(xx[k], ww0[k], a0);
            a1 = ffma2(xx[k], ww1[k], a1);
            a2 = ffma2(xx[k], ww2[k], a2);
            aS = fmaf(x[k], wS[k], aS);
        }
        a0 = ffma2(hhx0, ww0[7], a0);  a1 = ffma2(hhx0, ww1[7], a1);  a2 = ffma2(hhx0, ww2[7], a2);
        a0 = ffma2(hhx1, ww0[8], a0);  a1 = ffma2(hhx1, ww1[8], a1);  a2 = ffma2(hhx1, ww2[8], a2);
        a0 = ffma2(hhx2, ww0[9], a0);  a1 = ffma2(hhx2, ww1[9], a1);  a2 = ffma2(hhx2, ww2[9], a2);
        a0 = ffma2(hhx3, ww0[10], a0); a1 = ffma2(hhx3, ww1[10], a1); a2 = ffma2(hhx3, ww2[10], a2);
        aS = fmaf(hh0, wS[7], aS);
        aS = fmaf(hh1, wS[8], aS);
        aS = fmaf(hh2, wS[9], aS);
        aS = fmaf(hh3, wS[10], aS);

        float z0, z1, z2, z3, z4, zp0;
        upk(a0, z0, z1); upk(a1, z2, z3); upk(a2, z4, zp0);

        // activations: t_j = tanh(0.5 z_j) (c_j = 0.5 t_j + 0.5, folded below)
        const float t0 = ftanh(z0), t1 = ftanh(z1), t2 = ftanh(z2),
                    t3 = ftanh(z3), t4 = ftanh(z4);
        const float p0 = ftanh(zp0), p1 = ftanh(aS);

        // ---- ploss: packed Wp2 partials (bpp2 folded into lo-lane init)
        //      + single-depth quad reduce (3 independent shfls) ----
        const u64 p0p = pk1(p0), p1p = pk1(p1);
        u64 PPlo = ffma2(p0p, wpa01, ffma2(p1p, wpb01, bpc));
        u64 PPhi = ffma2(p0p, wpa23, fmul2(p1p, wpb23));
        float PP0, PP1, PP2, PP3;
        upk(PPlo, PP0, PP1); upk(PPhi, PP2, PP3);
        const float q1 = __shfl_xor_sync(0xffffffffu, PP1, 1);  // independent
        const float q2 = __shfl_xor_sync(0xffffffffu, PP2, 2);  // independent
        const float q3 = __shfl_xor_sync(0xffffffffu, PP3, 3);  // independent
        const float ploss = fabsf((PP0 + q1) + (q2 + q3));

        // ---- temp diffusion, packed:  sum d_j c_j = 0.5 (sum d_j t_j + sum d_j)
        //      dd01 = (hh1,hh2) - hh0;  dd23 = (hh3,x0) - hh0;  d4 scalar ----
        const u64 h12  = pk(hh1, hh2);
        const u64 h3x0 = pk(hh3, x[0]);
        const u64 dd01 = ffma2(hhx0, negone2, h12);
        const u64 dd23 = ffma2(hhx0, negone2, h3x0);
        const float d4 = x[1] - hh0;

        const u64 tt01 = pk(t0, t1);
        const u64 tt23 = pk(t2, t3);
        u64 s1p = fmul2(dd01, tt01);
        s1p = ffma2(dd23, tt23, s1p);
        float s1lo, s1hi;
        upk(s1p, s1lo, s1hi);
        const float S1 = fmaf(d4, t4, s1lo + s1hi);

        const u64 s2p = fadd2(dd01, dd23);
        float s2lo, s2hi;
        upk(s2p, s2lo, s2hi);
        const float S2 = (s2lo + s2hi) + d4;

        float nh = fmaf(gain, ploss, hh0);
        nh = fmaf(gainH, S1 + S2, nh);
        nh = fminf(fmaxf(nh, -1.0f), 5.0f);

        // ---- all-gather new state: three independent single-depth shfls ----
        const float g1 = __shfl_xor_sync(0xffffffffu, nh, 1);
        const float g2 = __shfl_xor_sync(0xffffffffu, nh, 2);
        const float g3 = __shfl_xor_sync(0xffffffffu, nh, 3);
        hh0 = nh; hh1 = g1; hh2 = g2; hh3 = g3;
        hhx0 = pk1(hh0); hhx1 = pk1(hh1); hhx2 = pk1(hh2); hhx3 = pk1(hh3);

        // rotate input buffers (renamed away by ptxas under the 2x unroll)
#pragma unroll
        for (int k = 0; k < 7; ++k) { x[k] = xn[k]; xx[k] = pk1(xn[k]); }
        xp = xnp;
        outp += ostride;
    }

    // final_state appended after outputs
    out[(size_t)T * B * 4 + (size_t)b * 4 + r] = hh0;
}

extern "C" void kernel_launch(void* const* d_in, const int* in_sizes, int n_in,
                              void* d_out, int out_size)
{
    const float* inp   = (const float*)d_in[0];
    const float* state = (const float*)d_in[1];
    const float* caps  = (const float*)d_in[2];
    const float* W1    = (const float*)d_in[3];
    const float* b1    = (const float*)d_in[4];
    const float* Wp1   = (const float*)d_in[5];
    const float* bp1   = (const float*)d_in[6];
    const float* Wp2   = (const float*)d_in[7];
    const float* bp2   = (const float*)d_in[8];
    const int*   adj   = (const int*)d_in[9];   // [4, 6]

    const int B = in_sizes[1] / 4;        // state is [B, 4]
    const int T = in_sizes[0] / (B * 7);  // inp is [T, B, 7]

    const int threads = 4 * B;
    const int block = 32;
    const int grid = (threads + block - 1) / block;

    diffeq_scan_kernel<<<grid, block>>>(inp, state, caps, W1, b1, Wp1, bp1,
                                        Wp2, bp2, adj, (float*)d_out, B, T);
}

// round 17
// speedup vs baseline: 1.4070x; 1.4070x over previous
#include <cuda_runtime.h>
#include <cstddef>

// DiffEqLayer scan: T steps, B chains, 4 threads/chain (role r = output row).
// Role-relative state hh[k] = h[r^k]; weights permuted at load; dots+epilogue
// packed into f32x2 (FFMA2); quad comm via single-depth shfl_xor 1/2/3.
//
// R16 measurement: 520.9 us, issue 19.5%, fma 18%, all pipes idle -> warps
// stall ~760 cyc/step on DRAM-latency input loads (1-iteration prefetch slack
// only covered ~190 cyc of ~1000-cyc NAT DRAM latency). Fix: two-level load
// pipeline: prefetch.global.L2 at distance 8 (DRAM->L2, issue-only) + register
// load ring at distance 2 (L2 ~405 cyc covered by ~380 cyc of slack).

typedef unsigned long long u64;

__device__ __forceinline__ float ftanh(float x) {
    float y;
    asm("tanh.approx.f32 %0, %1;" : "=f"(y) : "f"(x));
    return y;
}
__device__ __forceinline__ u64 pk(float lo, float hi) {
    u64 r;
    asm("mov.b64 %0, {%1, %2};" : "=l"(r) : "f"(lo), "f"(hi));
    return r;
}
__device__ __forceinline__ u64 pk1(float v) {  // (v, v)
    u64 r;
    asm("mov.b64 %0, {%1, %1};" : "=l"(r) : "f"(v));
    return r;
}
__device__ __forceinline__ void upk(u64 p, float& lo, float& hi) {
    asm("mov.b64 {%0, %1}, %2;" : "=f"(lo), "=f"(hi) : "l"(p));
}
__device__ __forceinline__ u64 ffma2(u64 a, u64 b, u64 c) {
    u64 d;
    asm("fma.rn.f32x2 %0, %1, %2, %3;" : "=l"(d) : "l"(a), "l"(b), "l"(c));
    return d;
}
__device__ __forceinline__ u64 fmul2(u64 a, u64 b) {
    u64 d;
    asm("mul.rn.f32x2 %0, %1, %2;" : "=l"(d) : "l"(a), "l"(b));
    return d;
}
__device__ __forceinline__ u64 fadd2(u64 a, u64 b) {
    u64 d;
    asm("add.rn.f32x2 %0, %1, %2;" : "=l"(d) : "l"(a), "l"(b));
    return d;
}
__device__ __forceinline__ float ldcs(const float* p) {
    float v;
    asm volatile("ld.global.cs.f32 %0, [%1];" : "=f"(v) : "l"(p));
    return v;
}
__device__ __forceinline__ void stcs(float* p, float v) {
    asm volatile("st.global.cs.f32 [%0], %1;" :: "l"(p), "f"(v));
}
__device__ __forceinline__ void pfL2(const float* p) {
    asm volatile("prefetch.global.L2 [%0];" :: "l"(p));
}

__global__ void __launch_bounds__(32)
diffeq_scan_kernel(const float* __restrict__ inp,    // [T, B, 7]
                   const float* __restrict__ state,  // [B, 4]
                   const float* __restrict__ caps,   // [4]
                   const float* __restrict__ W1,     // [15, 11]
                   const float* __restrict__ b1,     // [15]
                   const float* __restrict__ Wp1,    // [8, 11]
                   const float* __restrict__ bp1,    // [8]
                   const float* __restrict__ Wp2,    // [4, 8]
                   const float* __restrict__ bp2,    // [4]
                   const int*   __restrict__ adj,    // [4, 6]
                   float* __restrict__ out,          // [T*B*4 + B*4]
                   int B, int T)
{
    const int tid = blockIdx.x * blockDim.x + threadIdx.x;
    const int b = tid >> 2;
    const int r = tid & 3;
    if (b >= B) return;

    // ---- W1 row indices for this role, straight from adj_mat -------------
    int w1rows[5];
#pragma unroll
    for (int m = 0; m < 3; ++m) w1rows[m] = __ldg(&adj[r * 6 + (r ^ (m + 1))]);
    w1rows[3] = __ldg(&adj[r * 6 + 4]);
    w1rows[4] = __ldg(&adj[r * 6 + 5]);

    // ---- packed loop-invariant weights -----------------------------------
    float wrow[5][11];
#pragma unroll
    for (int m = 0; m < 5; ++m) {
        const int row = w1rows[m];
#pragma unroll
        for (int k = 0; k < 7; ++k) wrow[m][k] = 0.5f * __ldg(&W1[row * 11 + k]);
#pragma unroll
        for (int k = 0; k < 4; ++k)
            wrow[m][7 + k] = 0.5f * __ldg(&W1[row * 11 + 7 + (r ^ k)]);
    }
    float prow[2][11];
#pragma unroll
    for (int m = 0; m < 2; ++m) {
        const int row = 2 * r + m;
#pragma unroll
        for (int k = 0; k < 7; ++k) prow[m][k] = __ldg(&Wp1[row * 11 + k]);
#pragma unroll
        for (int k = 0; k < 4; ++k)
            prow[m][7 + k] = __ldg(&Wp1[row * 11 + 7 + (r ^ k)]);
    }
    u64 ww0[11], ww1[11], ww2[11];
    float wS[11];
#pragma unroll
    for (int k = 0; k < 11; ++k) {
        ww0[k] = pk(wrow[0][k], wrow[1][k]);
        ww1[k] = pk(wrow[2][k], wrow[3][k]);
        ww2[k] = pk(wrow[4][k], prow[0][k]);
        wS[k]  = prow[1][k];
    }
    const u64 bb0  = pk(0.5f * __ldg(&b1[w1rows[0]]), 0.5f * __ldg(&b1[w1rows[1]]));
    const u64 bb1_ = pk(0.5f * __ldg(&b1[w1rows[2]]), 0.5f * __ldg(&b1[w1rows[3]]));
    const u64 bb2_ = pk(0.5f * __ldg(&b1[w1rows[4]]), __ldg(&bp1[2 * r]));
    const float bS = __ldg(&bp1[2 * r + 1]);

    const u64 wpa01 = pk(__ldg(&Wp2[(r ^ 0) * 8 + 2 * r]), __ldg(&Wp2[(r ^ 1) * 8 + 2 * r]));
    const u64 wpa23 = pk(__ldg(&Wp2[(r ^ 2) * 8 + 2 * r]), __ldg(&Wp2[(r ^ 3) * 8 + 2 * r]));
    const u64 wpb01 = pk(__ldg(&Wp2[(r ^ 0) * 8 + 2 * r + 1]), __ldg(&Wp2[(r ^ 1) * 8 + 2 * r + 1]));
    const u64 wpb23 = pk(__ldg(&Wp2[(r ^ 2) * 8 + 2 * r + 1]), __ldg(&Wp2[(r ^ 3) * 8 + 2 * r + 1]));
    const u64 bpc = pk(__ldg(&bp2[r]), 0.0f);

    const float gain  = 0.5f * exp2f(__ldg(&caps[r]) * 3.321928094887362f);
    const float gainH = 0.5f * gain;
    const u64 negone2 = pk(-1.0f, -1.0f);

    // ---- role-relative state ---------------------------------------------
    float hh0 = __ldg(&state[b * 4 + r]);
    float hh1 = __ldg(&state[b * 4 + (r ^ 1)]);
    float hh2 = __ldg(&state[b * 4 + (r ^ 2)]);
    float hh3 = __ldg(&state[b * 4 + (r ^ 3)]);
    u64 hhx0 = pk1(hh0), hhx1 = pk1(hh1), hhx2 = pk1(hh2), hhx3 = pk1(hh3);

    const size_t xstride = (size_t)B * 7;
    const size_t pfoff   = 8 * xstride;   // L2-prefetch distance (iterations)
    const float* xp = inp + (size_t)b * 7;

    // register load ring: x (t), xn (t+1), xn2 loaded in-loop at t+2
    float x[7], xn[7];
    u64 xx[7];
#pragma unroll
    for (int k = 0; k < 7; ++k) { x[k] = ldcs(&xp[k]); xx[k] = pk1(x[k]); }
    if (T > 1) {
#pragma unroll
        for (int k = 0; k < 7; ++k) xn[k] = ldcs(&xp[xstride + k]);
    }
    // warm the L2 pipeline for the first few iterations
#pragma unroll
    for (int d = 2; d < 8; ++d)
        if (d < T) pfL2(xp + (size_t)d * xstride);

    const size_t ostride = (size_t)B * 4;
    float* outp = out + (size_t)b * 4 + r;

#pragma unroll 2
    for (int t = 0; t < T; ++t) {
        // issue t+2 loads first (earliest into the L1tex queue)
        float xn2[7];
        const float* xn2p = xp + 2 * xstride;
        if (t + 2 < T) {
#pragma unroll
            for (int k = 0; k < 7; ++k) xn2[k] = ldcs(&xn2p[k]);
        }
        // DRAM->L2 prefetch, 8 iterations ahead (issue-only, no scoreboard)
        if (t + 8 < T) pfL2(xp + pfoff);

        // outputs[t] = h(t) (state BEFORE update); streaming store
        stcs(outp, hh0);

        // ---- packed dot products (x terms first, h terms last) ----
        u64 a0 = bb0, a1 = bb1_, a2 = bb2_;
        float aS = bS;
#pragma unroll
        for (int k = 0; k < 7; ++k) {
            a0 = ffma2(xx[k], ww0[k], a0);
            a1 = ffma2(xx[k], ww1[k], a1);
            a2 = ffma2(xx[k], ww2[k], a2);
            aS = fmaf(x[k], wS[k], aS);
        }
        a0 = ffma2(hhx0, ww0[7], a0);  a1 = ffma2(hhx0, ww1[7], a1);  a2 = ffma2(hhx0, ww2[7], a2);
        a0 = ffma2(hhx1, ww0[8], a0);  a1 = ffma2(hhx1, ww1[8], a1);  a2 = ffma2(hhx1, ww2[8], a2);
        a0 = ffma2(hhx2, ww0[9], a0);  a1 = ffma2(hhx2, ww1[9], a1);  a2 = ffma2(hhx2, ww2[9], a2);
        a0 = ffma2(hhx3, ww0[10], a0); a1 = ffma2(hhx3, ww1[10], a1); a2 = ffma2(hhx3, ww2[10], a2);
        aS = fmaf(hh0, wS[7], aS);
        aS = fmaf(hh1, wS[8], aS);
        aS = fmaf(hh2, wS[9], aS);
        aS = fmaf(hh3, wS[10], aS);

        float z0, z1, z2, z3, z4, zp0;
        upk(a0, z0, z1); upk(a1, z2, z3); upk(a2, z4, zp0);

        const float t0 = ftanh(z0), t1 = ftanh(z1), t2 = ftanh(z2),
                    t3 = ftanh(z3), t4 = ftanh(z4);
        const float p0 = ftanh(zp0), p1 = ftanh(aS);

        // ---- ploss: packed Wp2 partials + single-depth quad reduce ----
        const u64 p0p = pk1(p0), p1p = pk1(p1);
        u64 PPlo = ffma2(p0p, wpa01, ffma2(p1p, wpb01, bpc));
        u64 PPhi = ffma2(p0p, wpa23, fmul2(p1p, wpb23));
        float PP0, PP1, PP2, PP3;
        upk(PPlo, PP0, PP1); upk(PPhi, PP2, PP3);
        const float q1 = __shfl_xor_sync(0xffffffffu, PP1, 1);
        const float q2 = __shfl_xor_sync(0xffffffffu, PP2, 2);
        const float q3 = __shfl_xor_sync(0xffffffffu, PP3, 3);
        const float ploss = fabsf((PP0 + q1) + (q2 + q3));

        // ---- temp diffusion, packed ----
        const u64 h12  = pk(hh1, hh2);
        const u64 h3x0 = pk(hh3, x[0]);
        const u64 dd01 = ffma2(hhx0, negone2, h12);
        const u64 dd23 = ffma2(hhx0, negone2, h3x0);
        const float d4 = x[1] - hh0;

        const u64 tt01 = pk(t0, t1);
        const u64 tt23 = pk(t2, t3);
        u64 s1p = fmul2(dd01, tt01);
        s1p = ffma2(dd23, tt23, s1p);
        float s1lo, s1hi;
        upk(s1p, s1lo, s1hi);
        const float S1 = fmaf(d4, t4, s1lo + s1hi);

        const u64 s2p = fadd2(dd01, dd23);
        float s2lo, s2hi;
        upk(s2p, s2lo, s2hi);
        const float S2 = (s2lo + s2hi) + d4;

        float nh = fmaf(gain, ploss, hh0);
        nh = fmaf(gainH, S1 + S2, nh);
        nh = fminf(fmaxf(nh, -1.0f), 5.0f);

        // ---- all-gather new state: three independent single-depth shfls ----
        const float g1 = __shfl_xor_sync(0xffffffffu, nh, 1);
        const float g2 = __shfl_xor_sync(0xffffffffu, nh, 2);
        const float g3 = __shfl_xor_sync(0xffffffffu, nh, 3);
        hh0 = nh; hh1 = g1; hh2 = g2; hh3 = g3;
        hhx0 = pk1(hh0); hhx1 = pk1(hh1); hhx2 = pk1(hh2); hhx3 = pk1(hh3);

        // rotate the 3-deep load ring (partially renamed under unroll 2)
#pragma unroll
        for (int k = 0; k < 7; ++k) {
            x[k] = xn[k]; xx[k] = pk1(xn[k]); xn[k] = xn2[k];
        }
        xp += xstride;
        outp += ostride;
    }

    // final_state appended after outputs
    out[(size_t)T * B * 4 + (size_t)b * 4 + r] = hh0;
}

extern "C" void kernel_launch(void* const* d_in, const int* in_sizes, int n_in,
                              void* d_out, int out_size)
{
    const float* inp   = (const float*)d_in[0];
    const float* state = (const float*)d_in[1];
    const float* caps  = (const float*)d_in[2];
    const float* W1    = (const float*)d_in[3];
    const float* b1    = (const float*)d_in[4];
    const float* Wp1   = (const float*)d_in[5];
    const float* bp1   = (const float*)d_in[6];
    const float* Wp2   = (const float*)d_in[7];
    const float* bp2   = (const float*)d_in[8];
    const int*   adj   = (const int*)d_in[9];   // [4, 6]

    const int B = in_sizes[1] / 4;        // state is [B, 4]
    const int T = in_sizes[0] / (B * 7);  // inp is [T, B, 7]

    const int threads = 4 * B;
    const int block = 32;
    const int grid = (threads + block - 1) / block;

    diffeq_scan_kernel<<<grid, block>>>(inp, state, caps, W1, b1, Wp1, bp1,
                                        Wp2, bp2, adj, (float*)d_out, B, T);
}